// round 3
// baseline (speedup 1.0000x reference)
#include <cuda_runtime.h>

// SampleConditionalGMM: out = stds[b, lut[label], c] * noise + means[b, lut[label], c]
// Shapes: label_map [2,160,160,160,1] i32, means/stds [2,25,2] f32,
//         noise/out [2,160,160,160,2] f32.

#define NL 25          // number of generation labels
#define MAXL 48        // max label value + 1
#define VOX 4096000    // 160*160*160 voxels per batch
#define VPT 8          // voxels per thread
#define VPB 2048       // voxels per block (256 threads * 8)
#define BLOCKS_PER_BATCH (VOX / VPB)   // 2000

__constant__ int c_gen_labels[NL] = {
    0, 2, 3, 4, 5, 7, 8, 10, 11, 12, 13, 14, 15, 16, 17, 18,
    24, 26, 28, 41, 42, 43, 44, 46, 47
};

__global__ __launch_bounds__(256)
void gmm_sample_kernel(const int*   __restrict__ label,
                       const float* __restrict__ means,
                       const float* __restrict__ stds,
                       const float* __restrict__ noise,
                       float*       __restrict__ out)
{
    // One float4 per label VALUE: {std_c0, std_c1, mean_c0, mean_c1}.
    // One LDS.128 per voxel replaces four scalar LDS.
    __shared__ float4 s_tab[MAXL];

    const int t = threadIdx.x;
    const int b = blockIdx.x / BLOCKS_PER_BATCH;   // batch id, constant per block

    if (t < NL) {
        const int lbl = c_gen_labels[t];
        const float2 m = *reinterpret_cast<const float2*>(means + (b * NL + t) * 2);
        const float2 s = *reinterpret_cast<const float2*>(stds  + (b * NL + t) * 2);
        s_tab[lbl] = make_float4(s.x, s.y, m.x, m.y);
    }
    __syncthreads();

    const long long v = (long long)blockIdx.x * VPB + (long long)t * VPT;

    // 8 labels via two int4 loads
    const int4 la = *reinterpret_cast<const int4*>(label + v);
    const int4 lc = *reinterpret_cast<const int4*>(label + v + 4);

    // 16 noise floats via four float4 loads
    const float4* np = reinterpret_cast<const float4*>(noise + v * 2);
    const float4 n0 = np[0];
    const float4 n1 = np[1];
    const float4 n2 = np[2];
    const float4 n3 = np[3];

    // Gather per-voxel {std0,std1,mean0,mean1} with one LDS.128 each
    const float4 t0 = s_tab[la.x];
    const float4 t1 = s_tab[la.y];
    const float4 t2 = s_tab[la.z];
    const float4 t3 = s_tab[la.w];
    const float4 t4 = s_tab[lc.x];
    const float4 t5 = s_tab[lc.y];
    const float4 t6 = s_tab[lc.z];
    const float4 t7 = s_tab[lc.w];

    float4 o0, o1, o2, o3;
    o0.x = fmaf(t0.x, n0.x, t0.z);  o0.y = fmaf(t0.y, n0.y, t0.w);
    o0.z = fmaf(t1.x, n0.z, t1.z);  o0.w = fmaf(t1.y, n0.w, t1.w);
    o1.x = fmaf(t2.x, n1.x, t2.z);  o1.y = fmaf(t2.y, n1.y, t2.w);
    o1.z = fmaf(t3.x, n1.z, t3.z);  o1.w = fmaf(t3.y, n1.w, t3.w);
    o2.x = fmaf(t4.x, n2.x, t4.z);  o2.y = fmaf(t4.y, n2.y, t4.w);
    o2.z = fmaf(t5.x, n2.z, t5.z);  o2.w = fmaf(t5.y, n2.w, t5.w);
    o3.x = fmaf(t6.x, n3.x, t6.z);  o3.y = fmaf(t6.y, n3.y, t6.w);
    o3.z = fmaf(t7.x, n3.z, t7.z);  o3.w = fmaf(t7.y, n3.w, t7.w);

    float4* op = reinterpret_cast<float4*>(out + v * 2);
    op[0] = o0;
    op[1] = o1;
    op[2] = o2;
    op[3] = o3;
}

extern "C" void kernel_launch(void* const* d_in, const int* in_sizes, int n_in,
                              void* d_out, int out_size)
{
    const int*   label = (const int*)  d_in[0];  // [2,160,160,160,1]
    const float* means = (const float*)d_in[1];  // [2,25,2]
    const float* stds  = (const float*)d_in[2];  // [2,25,2]
    const float* noise = (const float*)d_in[3];  // [2,160,160,160,2]
    float*       out   = (float*)d_out;

    const int blocks = 2 * BLOCKS_PER_BATCH;     // 4000
    gmm_sample_kernel<<<blocks, 256>>>(label, means, stds, noise, out);
}

// round 4
// speedup vs baseline: 1.1580x; 1.1580x over previous
#include <cuda_runtime.h>

// SampleConditionalGMM: out = stds[b, lut[label], c] * noise + means[b, lut[label], c]
// Shapes: label_map [2,160,160,160,1] i32, means/stds [2,25,2] f32,
//         noise/out [2,160,160,160,2] f32.
//
// Gather strategy: shared table holds one float4 {std0,std1,mean0,mean1} per
// label VALUE, replicated 8x across the float4-columns of the crossbar.
// Each thread reads s_tab[lbl*8 + (tid&7)]: within every 8-lane phase of the
// LDS.128, lanes hit 8 distinct columns -> conflict-free for ANY label mix.

#define NL 25          // number of generation labels
#define MAXL 48        // max label value + 1
#define REP 8          // replication factor (float4 columns per 128B row)
#define VOX 4096000    // 160*160*160 voxels per batch
#define VPT 4          // voxels per thread
#define VPB 1024       // voxels per block (256 threads * 4)
#define BLOCKS_PER_BATCH (VOX / VPB)   // 4000

__constant__ int c_gen_labels[NL] = {
    0, 2, 3, 4, 5, 7, 8, 10, 11, 12, 13, 14, 15, 16, 17, 18,
    24, 26, 28, 41, 42, 43, 44, 46, 47
};

__global__ __launch_bounds__(256)
void gmm_sample_kernel(const int*   __restrict__ label,
                       const float* __restrict__ means,
                       const float* __restrict__ stds,
                       const float* __restrict__ noise,
                       float*       __restrict__ out)
{
    __shared__ float4 s_tab[MAXL * REP];   // 6144 B

    const int t = threadIdx.x;
    const int b = blockIdx.x / BLOCKS_PER_BATCH;   // batch id, constant per block

    // Fill: 25 labels x 8 replicas = 200 float4, one STS.128 per thread.
    if (t < NL * REP) {
        const int li  = t >> 3;        // compacted label index 0..24
        const int col = t & 7;         // replica column
        const int lbl = c_gen_labels[li];
        const float2 m = *reinterpret_cast<const float2*>(means + (b * NL + li) * 2);
        const float2 s = *reinterpret_cast<const float2*>(stds  + (b * NL + li) * 2);
        s_tab[lbl * REP + col] = make_float4(s.x, s.y, m.x, m.y);
    }
    __syncthreads();

    const long long v = (long long)blockIdx.x * VPB + (long long)t * VPT;

    const int4 lb = *reinterpret_cast<const int4*>(label + v);

    const float4* np = reinterpret_cast<const float4*>(noise + v * 2);
    const float4 n0 = np[0];
    const float4 n1 = np[1];

    const int col = t & 7;   // fixed conflict-free column for this lane

    const float4 t0 = s_tab[lb.x * REP + col];
    const float4 t1 = s_tab[lb.y * REP + col];
    const float4 t2 = s_tab[lb.z * REP + col];
    const float4 t3 = s_tab[lb.w * REP + col];

    float4 o0, o1;
    o0.x = fmaf(t0.x, n0.x, t0.z);  o0.y = fmaf(t0.y, n0.y, t0.w);
    o0.z = fmaf(t1.x, n0.z, t1.z);  o0.w = fmaf(t1.y, n0.w, t1.w);
    o1.x = fmaf(t2.x, n1.x, t2.z);  o1.y = fmaf(t2.y, n1.y, t2.w);
    o1.z = fmaf(t3.x, n1.z, t3.z);  o1.w = fmaf(t3.y, n1.w, t3.w);

    float4* op = reinterpret_cast<float4*>(out + v * 2);
    op[0] = o0;
    op[1] = o1;
}

extern "C" void kernel_launch(void* const* d_in, const int* in_sizes, int n_in,
                              void* d_out, int out_size)
{
    const int*   label = (const int*)  d_in[0];  // [2,160,160,160,1]
    const float* means = (const float*)d_in[1];  // [2,25,2]
    const float* stds  = (const float*)d_in[2];  // [2,25,2]
    const float* noise = (const float*)d_in[3];  // [2,160,160,160,2]
    float*       out   = (float*)d_out;

    const int blocks = 2 * BLOCKS_PER_BATCH;     // 8000
    gmm_sample_kernel<<<blocks, 256>>>(label, means, stds, noise, out);
}